// round 15
// baseline (speedup 1.0000x reference)
#include <cuda_runtime.h>
#include <cuda_fp16.h>
#include <cuda_bf16.h>
#include <math.h>

#define NNODES 100000
#define NEDGES 3200000
#define NFEAT  256
#define NHID   128
#define NCLASS 40

// ---------------- scratch (static device globals; no allocs) ----------------
__device__ __half         g_sh[(size_t)NNODES * NHID];   // self proj fp16
__device__ __half         g_zh[(size_t)NNODES * NHID];   // neigh proj fp16
__device__ __nv_bfloat16  g_hb[(size_t)NNODES * NHID];   // layer output bf16
__device__ __nv_bfloat16  g_xb[(size_t)NNODES * NFEAT];  // x in bf16
__device__ __nv_bfloat16  g_w1b[NHID * 2 * NFEAT];
__device__ __nv_bfloat16  g_w2b[NHID * 2 * NHID];
__device__ int            g_deg[NNODES];
__device__ int            g_rowptr[NNODES + 1];
__device__ int            g_cursor[NNODES];
__device__ int            g_col[NEDGES];

// ---------------- helpers ----------------
__device__ __forceinline__ unsigned pack_bf16x2(float lo, float hi) {
    unsigned u;
    asm("cvt.rn.bf16x2.f32 %0, %1, %2;" : "=r"(u) : "f"(hi), "f"(lo));
    return u;
}
__device__ __forceinline__ unsigned f2tf32(float v) {
    unsigned u;
    asm("cvt.rna.tf32.f32 %0, %1;" : "=r"(u) : "f"(v));
    return u;
}
__device__ __forceinline__ void mma_bf16(float* c, const unsigned* a,
                                         unsigned b0, unsigned b1) {
    asm volatile(
        "mma.sync.aligned.m16n8k16.row.col.f32.bf16.bf16.f32 "
        "{%0,%1,%2,%3}, {%4,%5,%6,%7}, {%8,%9}, {%0,%1,%2,%3};"
        : "+f"(c[0]), "+f"(c[1]), "+f"(c[2]), "+f"(c[3])
        : "r"(a[0]), "r"(a[1]), "r"(a[2]), "r"(a[3]), "r"(b0), "r"(b1));
}
__device__ __forceinline__ void mma_tf32(float* c, const unsigned* a,
                                         unsigned b0, unsigned b1) {
    asm volatile(
        "mma.sync.aligned.m16n8k8.row.col.f32.tf32.tf32.f32 "
        "{%0,%1,%2,%3}, {%4,%5,%6,%7}, {%8,%9}, {%0,%1,%2,%3};"
        : "+f"(c[0]), "+f"(c[1]), "+f"(c[2]), "+f"(c[3])
        : "r"(a[0]), "r"(a[1]), "r"(a[2]), "r"(a[3]), "r"(b0), "r"(b1));
}
__device__ __forceinline__ unsigned s2u(const void* p) {
    return (unsigned)__cvta_generic_to_shared(p);
}
__device__ __forceinline__ void cp16(unsigned dst, const void* src, bool pred) {
    int sz = pred ? 16 : 0;
    asm volatile("cp.async.cg.shared.global [%0], [%1], 16, %2;"
                 :: "r"(dst), "l"(src), "r"(sz));
}
#define CP_COMMIT() asm volatile("cp.async.commit_group;")
#define CP_WAIT1()  asm volatile("cp.async.wait_group 1;")
#define CP_WAIT0()  asm volatile("cp.async.wait_group 0;")

// ---------------- fp32 -> bf16 convert ----------------
__global__ void k_cvt(const float* __restrict__ in, __nv_bfloat16* __restrict__ out,
                      int n4) {
    int i = blockIdx.x * blockDim.x + threadIdx.x;
    if (i < n4) {
        float4 v = ((const float4*)in)[i];
        ((uint2*)out)[i] = make_uint2(pack_bf16x2(v.x, v.y), pack_bf16x2(v.z, v.w));
    }
}

// ---------------- CSR build (4 edges / thread) ----------------
__global__ void k_count(const int* __restrict__ rows, int* __restrict__ deg) {
    int i = blockIdx.x * blockDim.x + threadIdx.x;
    if (i < NEDGES / 4) {
        int4 r = ((const int4*)rows)[i];
        atomicAdd(&deg[r.x], 1);
        atomicAdd(&deg[r.y], 1);
        atomicAdd(&deg[r.z], 1);
        atomicAdd(&deg[r.w], 1);
    }
}

__global__ void k_scan(const int* __restrict__ deg, int* __restrict__ rp,
                       int* __restrict__ cur) {
    __shared__ int wsum[32];
    __shared__ int carry;
    int tid = threadIdx.x, lane = tid & 31, wid = tid >> 5;
    if (tid == 0) carry = 0;
    __syncthreads();
    for (int base = 0; base < NNODES; base += 1024) {
        int i = base + tid;
        int v = (i < NNODES) ? deg[i] : 0;
        int x = v;
        #pragma unroll
        for (int d = 1; d < 32; d <<= 1) {
            int y = __shfl_up_sync(0xffffffffu, x, d);
            if (lane >= d) x += y;
        }
        if (lane == 31) wsum[wid] = x;
        __syncthreads();
        if (wid == 0) {
            int s = wsum[lane];
            #pragma unroll
            for (int d = 1; d < 32; d <<= 1) {
                int y = __shfl_up_sync(0xffffffffu, s, d);
                if (lane >= d) s += y;
            }
            wsum[lane] = s;
        }
        __syncthreads();
        int off  = carry + (wid ? wsum[wid - 1] : 0);
        int excl = off + x - v;
        if (i < NNODES) { rp[i] = excl; cur[i] = excl; }
        int tot = wsum[31];
        __syncthreads();
        if (tid == 0) carry += tot;
        __syncthreads();
    }
    if (tid == 0) rp[NNODES] = carry;
}

__global__ void k_fill(const int* __restrict__ rows, const int* __restrict__ cols,
                       int* __restrict__ cur, int* __restrict__ col) {
    int i = blockIdx.x * blockDim.x + threadIdx.x;
    if (i < NEDGES / 4) {
        int4 r = ((const int4*)rows)[i];
        int4 c = ((const int4*)cols)[i];
        col[atomicAdd(&cur[r.x], 1)] = c.x;
        col[atomicAdd(&cur[r.y], 1)] = c.y;
        col[atomicAdd(&cur[r.z], 1)] = c.z;
        col[atomicAdd(&cur[r.w], 1)] = c.w;
    }
}

// ---------------- pipelined bf16 GEMM (outputs fp16: s | z) — R10 version ----------------
#define PITCH 80
__global__ __launch_bounds__(256) void k_gemm_bf16(
    const __nv_bfloat16* __restrict__ A, int K,
    const __nv_bfloat16* __restrict__ W,
    __half* __restrict__ Csh, __half* __restrict__ Czh)
{
    __shared__ __align__(16) unsigned char smA[2][128 * PITCH];
    __shared__ __align__(16) unsigned char smB[2][128 * PITCH];
    const int tid = threadIdx.x, lane = tid & 31, wid = tid >> 5;
    const int warpM = wid & 3, warpN = wid >> 2;
    const int row0 = blockIdx.x * 128;
    const int ldw = 2 * K;
    const __nv_bfloat16* Wb = W + (size_t)blockIdx.y * K;
    __half* C = blockIdx.y ? Czh : Csh;
    const int NT = K >> 5;

    const int lr0 = tid >> 2, lc0 = tid & 3;
    const int lr1 = (tid + 256) >> 2, lc1 = lc0;
    const bool p0 = (row0 + lr0) < NNODES;
    const bool p1 = (row0 + lr1) < NNODES;

    float acc[2][8][4];
    #pragma unroll
    for (int mi = 0; mi < 2; mi++)
        #pragma unroll
        for (int ni = 0; ni < 8; ni++)
            #pragma unroll
            for (int q = 0; q < 4; q++) acc[mi][ni][q] = 0.f;

    {
        cp16(s2u(smA[0] + lr0 * PITCH + lc0 * 16),
             A + (size_t)(row0 + lr0) * K + lc0 * 8, p0);
        cp16(s2u(smA[0] + lr1 * PITCH + lc1 * 16),
             A + (size_t)(row0 + lr1) * K + lc1 * 8, p1);
        cp16(s2u(smB[0] + lr0 * PITCH + lc0 * 16),
             Wb + (size_t)lr0 * ldw + lc0 * 8, true);
        cp16(s2u(smB[0] + lr1 * PITCH + lc1 * 16),
             Wb + (size_t)lr1 * ldw + lc1 * 8, true);
        CP_COMMIT();
    }

    for (int kt = 0; kt < NT; kt++) {
        if (kt + 1 < NT) {
            int k0 = (kt + 1) << 5;
            int nb = (kt + 1) & 1;
            cp16(s2u(smA[nb] + lr0 * PITCH + lc0 * 16),
                 A + (size_t)(row0 + lr0) * K + k0 + lc0 * 8, p0);
            cp16(s2u(smA[nb] + lr1 * PITCH + lc1 * 16),
                 A + (size_t)(row0 + lr1) * K + k0 + lc1 * 8, p1);
            cp16(s2u(smB[nb] + lr0 * PITCH + lc0 * 16),
                 Wb + (size_t)lr0 * ldw + k0 + lc0 * 8, true);
            cp16(s2u(smB[nb] + lr1 * PITCH + lc1 * 16),
                 Wb + (size_t)lr1 * ldw + k0 + lc1 * 8, true);
            CP_COMMIT();
            CP_WAIT1();
        } else {
            CP_WAIT0();
        }
        __syncthreads();

        const unsigned char* Ab = smA[kt & 1];
        const unsigned char* Bb = smB[kt & 1];
        #pragma unroll
        for (int ks = 0; ks < 2; ks++) {
            const int q0 = ks * 8 + (lane & 3);
            unsigned af[2][4];
            #pragma unroll
            for (int mi = 0; mi < 2; mi++) {
                int r = warpM * 32 + mi * 16 + (lane >> 2);
                af[mi][0] = *(const unsigned*)(Ab + r * PITCH + q0 * 4);
                af[mi][1] = *(const unsigned*)(Ab + (r + 8) * PITCH + q0 * 4);
                af[mi][2] = *(const unsigned*)(Ab + r * PITCH + (q0 + 4) * 4);
                af[mi][3] = *(const unsigned*)(Ab + (r + 8) * PITCH + (q0 + 4) * 4);
            }
            #pragma unroll
            for (int ni = 0; ni < 8; ni++) {
                int n = warpN * 64 + ni * 8 + (lane >> 2);
                unsigned b0 = *(const unsigned*)(Bb + n * PITCH + q0 * 4);
                unsigned b1 = *(const unsigned*)(Bb + n * PITCH + (q0 + 4) * 4);
                mma_bf16(acc[0][ni], af[0], b0, b1);
                mma_bf16(acc[1][ni], af[1], b0, b1);
            }
        }
        __syncthreads();
    }

    #pragma unroll
    for (int mi = 0; mi < 2; mi++) {
        int rbase = row0 + warpM * 32 + mi * 16 + (lane >> 2);
        #pragma unroll
        for (int ni = 0; ni < 8; ni++) {
            int col = warpN * 64 + ni * 8 + 2 * (lane & 3);
            if (rbase < NNODES)
                *(__half2*)(C + (size_t)rbase * NHID + col) =
                    __floats2half2_rn(acc[mi][ni][0], acc[mi][ni][1]);
            if (rbase + 8 < NNODES)
                *(__half2*)(C + (size_t)(rbase + 8) * NHID + col) =
                    __floats2half2_rn(acc[mi][ni][2], acc[mi][ni][3]);
        }
    }
}

// ---------------- SpMM: h = relu(s + (A@z)/(deg+1)), 4-way MLP ----------------
__global__ __launch_bounds__(256) void k_spmm(const __half* __restrict__ zh,
                                              const __half* __restrict__ sh,
                                              const int* __restrict__ rp,
                                              const int* __restrict__ col,
                                              __nv_bfloat16* __restrict__ hb) {
    int lane = threadIdx.x & 31;
    int n    = (blockIdx.x * 256 + threadIdx.x) >> 5;
    if (n >= NNODES) return;
    int e = rp[n], end = rp[n + 1];
    int deg = end - e;
    float ax = 0.f, ay = 0.f, az = 0.f, aw = 0.f;
    for (; e + 4 <= end; e += 4) {
        int c0 = col[e], c1 = col[e + 1], c2 = col[e + 2], c3 = col[e + 3];
        uint2 u0 = *(const uint2*)(zh + (size_t)c0 * NHID + lane * 4);
        uint2 u1 = *(const uint2*)(zh + (size_t)c1 * NHID + lane * 4);
        uint2 u2 = *(const uint2*)(zh + (size_t)c2 * NHID + lane * 4);
        uint2 u3 = *(const uint2*)(zh + (size_t)c3 * NHID + lane * 4);
        float2 a0 = __half22float2(*(__half2*)&u0.x), a1 = __half22float2(*(__half2*)&u0.y);
        float2 b0 = __half22float2(*(__half2*)&u1.x), b1 = __half22float2(*(__half2*)&u1.y);
        float2 d0 = __half22float2(*(__half2*)&u2.x), d1 = __half22float2(*(__half2*)&u2.y);
        float2 e0 = __half22float2(*(__half2*)&u3.x), e1 = __half22float2(*(__half2*)&u3.y);
        ax += (a0.x + b0.x) + (d0.x + e0.x);
        ay += (a0.y + b0.y) + (d0.y + e0.y);
        az += (a1.x + b1.x) + (d1.x + e1.x);
        aw += (a1.y + b1.y) + (d1.y + e1.y);
    }
    for (; e < end; e++) {
        int c0 = col[e];
        uint2 u0 = *(const uint2*)(zh + (size_t)c0 * NHID + lane * 4);
        float2 a0 = __half22float2(*(__half2*)&u0.x), a1 = __half22float2(*(__half2*)&u0.y);
        ax += a0.x; ay += a0.y; az += a1.x; aw += a1.y;
    }
    float inv = 1.0f / (1.0f + (float)deg);
    uint2 su = *(const uint2*)(sh + (size_t)n * NHID + lane * 4);
    float2 s0 = __half22float2(*(__half2*)&su.x);
    float2 s1 = __half22float2(*(__half2*)&su.y);
    float ox = fmaxf(fmaf(ax, inv, s0.x), 0.f);
    float oy = fmaxf(fmaf(ay, inv, s0.y), 0.f);
    float oz = fmaxf(fmaf(az, inv, s1.x), 0.f);
    float ow = fmaxf(fmaf(aw, inv, s1.y), 0.f);
    *(uint2*)(hb + (size_t)n * NHID + lane * 4) =
        make_uint2(pack_bf16x2(ox, oy), pack_bf16x2(oz, ow));
}

// ---------------- MLP + log_softmax (tf32 MMA; A from bf16 h) ----------------
__global__ __launch_bounds__(128) void k_mlp_tc(const __nv_bfloat16* __restrict__ hb,
                                                const float* __restrict__ Wm,
                                                const float* __restrict__ b,
                                                float* __restrict__ out) {
    __shared__ unsigned As[32][132];
    __shared__ unsigned Bsm[NCLASS][132];
    __shared__ float    Ls[128][41];
    __shared__ float    bs[NCLASS];

    const int tid = threadIdx.x, lane = tid & 31, wid = tid >> 5;
    const int row0 = blockIdx.x * 128;

    for (int i = tid; i < NCLASS * NHID; i += 128)
        Bsm[i >> 7][i & 127] = f2tf32(Wm[i]);
    if (tid < NCLASS) bs[tid] = b[tid];

    float acc[2][5][4];
    #pragma unroll
    for (int mi = 0; mi < 2; mi++)
        #pragma unroll
        for (int ni = 0; ni < 5; ni++)
            #pragma unroll
            for (int q = 0; q < 4; q++) acc[mi][ni][q] = 0.f;

    for (int k0 = 0; k0 < NHID; k0 += 32) {
        #pragma unroll
        for (int j = 0; j < 8; j++) {
            int i  = tid + j * 128;
            int r  = i >> 3;
            int c4 = (i & 7) * 4;
            uint2 u = make_uint2(0u, 0u);
            if (row0 + r < NNODES)
                u = *(const uint2*)(hb + (size_t)(row0 + r) * NHID + k0 + c4);
            As[c4 + 0][r] = u.x << 16;
            As[c4 + 1][r] = u.x & 0xffff0000u;
            As[c4 + 2][r] = u.y << 16;
            As[c4 + 3][r] = u.y & 0xffff0000u;
        }
        __syncthreads();

        #pragma unroll
        for (int kk = 0; kk < 32; kk += 8) {
            const int kc = kk + (lane & 3);
            unsigned af[2][4];
            #pragma unroll
            for (int mi = 0; mi < 2; mi++) {
                int r = wid * 32 + mi * 16 + (lane >> 2);
                af[mi][0] = As[kc][r];
                af[mi][1] = As[kc][r + 8];
                af[mi][2] = As[kc + 4][r];
                af[mi][3] = As[kc + 4][r + 8];
            }
            #pragma unroll
            for (int ni = 0; ni < 5; ni++) {
                int n = ni * 8 + (lane >> 2);
                unsigned b0 = Bsm[n][k0 + kc];
                unsigned b1 = Bsm[n][k0 + kc + 4];
                mma_tf32(acc[0][ni], af[0], b0, b1);
                mma_tf32(acc[1][ni], af[1], b0, b1);
            }
        }
        __syncthreads();
    }

    #pragma unroll
    for (int mi = 0; mi < 2; mi++) {
        int r = wid * 32 + mi * 16 + (lane >> 2);
        #pragma unroll
        for (int ni = 0; ni < 5; ni++) {
            int c = ni * 8 + 2 * (lane & 3);
            Ls[r][c]         = acc[mi][ni][0];
            Ls[r][c + 1]     = acc[mi][ni][1];
            Ls[r + 8][c]     = acc[mi][ni][2];
            Ls[r + 8][c + 1] = acc[mi][ni][3];
        }
    }
    __syncthreads();

    int gr = row0 + tid;
    if (gr >= NNODES) return;
    float l[NCLASS];
    float m = -INFINITY;
    #pragma unroll
    for (int c = 0; c < NCLASS; c++) {
        l[c] = Ls[tid][c] + bs[c];
        m = fmaxf(m, l[c]);
    }
    float se = 0.f;
    #pragma unroll
    for (int c = 0; c < NCLASS; c++) se += expf(l[c] - m);
    float lse = m + logf(se);
    float* op = out + (size_t)gr * NCLASS;
    #pragma unroll
    for (int c = 0; c < NCLASS; c += 4)
        *(float4*)(op + c) = make_float4(l[c] - lse, l[c + 1] - lse,
                                         l[c + 2] - lse, l[c + 3] - lse);
}

// ---------------- launch ----------------
extern "C" void kernel_launch(void* const* d_in, const int* in_sizes, int n_in,
                              void* d_out, int out_size) {
    const float* x    = (const float*)d_in[0];
    const float* W1   = (const float*)d_in[1];
    const float* W2   = (const float*)d_in[2];
    const float* mW   = (const float*)d_in[3];
    const float* mb   = (const float*)d_in[4];
    const int*   rows = (const int*)d_in[5];
    const int*   cols = (const int*)d_in[6];
    float*       out  = (float*)d_out;

    __half *p_sh, *p_zh;
    __nv_bfloat16 *p_hb, *p_xb, *p_w1b, *p_w2b;
    int *p_deg, *p_rp, *p_cur, *p_col;
    cudaGetSymbolAddress((void**)&p_sh,  g_sh);
    cudaGetSymbolAddress((void**)&p_zh,  g_zh);
    cudaGetSymbolAddress((void**)&p_hb,  g_hb);
    cudaGetSymbolAddress((void**)&p_xb,  g_xb);
    cudaGetSymbolAddress((void**)&p_w1b, g_w1b);
    cudaGetSymbolAddress((void**)&p_w2b, g_w2b);
    cudaGetSymbolAddress((void**)&p_deg, g_deg);
    cudaGetSymbolAddress((void**)&p_rp,  g_rowptr);
    cudaGetSymbolAddress((void**)&p_cur, g_cursor);
    cudaGetSymbolAddress((void**)&p_col, g_col);

    static cudaStream_t s_side = nullptr;
    static cudaEvent_t  ev_fork = nullptr, ev_w = nullptr, ev_join = nullptr;
    if (s_side == nullptr) {
        cudaStreamCreate(&s_side);
        cudaEventCreateWithFlags(&ev_fork, cudaEventDisableTiming);
        cudaEventCreateWithFlags(&ev_w,    cudaEventDisableTiming);
        cudaEventCreateWithFlags(&ev_join, cudaEventDisableTiming);
    }

    const int GB_E4 = (NEDGES / 4 + 255) / 256;
    const int GB_W  = (NNODES * 32 + 255) / 256;
    const int GB_T  = (NNODES + 127) / 128;
    const dim3 GB_G(GB_T, 2);
    const int n4x  = NNODES * NFEAT / 4;
    const int n4w1 = NHID * 2 * NFEAT / 4;
    const int n4w2 = NHID * 2 * NHID / 4;

    // ---- fork: W cvts + CSR build on side stream ----
    cudaEventRecord(ev_fork, 0);
    cudaStreamWaitEvent(s_side, ev_fork, 0);
    k_cvt<<<(n4w1 + 255) / 256, 256, 0, s_side>>>(W1, p_w1b, n4w1);
    k_cvt<<<(n4w2 + 255) / 256, 256, 0, s_side>>>(W2, p_w2b, n4w2);
    cudaEventRecord(ev_w, s_side);
    cudaMemsetAsync(p_deg, 0, NNODES * sizeof(int), s_side);
    k_count<<<GB_E4, 256, 0, s_side>>>(rows, p_deg);
    k_scan<<<1, 1024, 0, s_side>>>(p_deg, p_rp, p_cur);
    k_fill<<<GB_E4, 256, 0, s_side>>>(rows, cols, p_cur, p_col);
    cudaEventRecord(ev_join, s_side);

    // ---- main: x conversion, then layer-1 GEMM (waits on W1 cvt) ----
    k_cvt<<<(n4x + 255) / 256, 256>>>(x, p_xb, n4x);
    cudaStreamWaitEvent(0, ev_w, 0);
    k_gemm_bf16<<<GB_G, 256>>>(p_xb, NFEAT, p_w1b, p_sh, p_zh);

    // ---- join: SpMM needs CSR + z + s ----
    cudaStreamWaitEvent(0, ev_join, 0);
    k_spmm<<<GB_W, 256>>>(p_zh, p_sh, p_rp, p_col, p_hb);

    // Layer 2 (w2b ordered via ev_join transitively)
    k_gemm_bf16<<<GB_G, 256>>>(p_hb, NHID, p_w2b, p_sh, p_zh);
    k_spmm<<<GB_W, 256>>>(p_zh, p_sh, p_rp, p_col, p_hb);

    // MLP + log_softmax
    k_mlp_tc<<<GB_T, 128>>>(p_hb, mW, mb, out);
}

// round 16
// speedup vs baseline: 1.1638x; 1.1638x over previous
#include <cuda_runtime.h>
#include <cuda_fp16.h>
#include <cuda_bf16.h>
#include <math.h>

#define NNODES 100000
#define NEDGES 3200000
#define NFEAT  256
#define NHID   128
#define NCLASS 40
#define SCAN_BLKS ((NNODES + 1023) / 1024)   // 98

// ---------------- scratch (static device globals; no allocs) ----------------
__device__ __half         g_sh[(size_t)NNODES * NHID];   // self proj fp16
__device__ __half         g_zh[(size_t)NNODES * NHID];   // neigh proj fp16
__device__ __nv_bfloat16  g_hb[(size_t)NNODES * NHID];   // layer output bf16
__device__ __nv_bfloat16  g_xb[(size_t)NNODES * NFEAT];  // x in bf16
__device__ __nv_bfloat16  g_w1b[NHID * 2 * NFEAT];
__device__ __nv_bfloat16  g_w2b[NHID * 2 * NHID];
__device__ int            g_deg[NNODES];
__device__ int            g_rowptr[NNODES + 1];
__device__ int            g_cursor[NNODES];
__device__ int            g_col[NEDGES];
__device__ int            g_blksum[SCAN_BLKS];

// ---------------- helpers ----------------
__device__ __forceinline__ unsigned pack_bf16x2(float lo, float hi) {
    unsigned u;
    asm("cvt.rn.bf16x2.f32 %0, %1, %2;" : "=r"(u) : "f"(hi), "f"(lo));
    return u;
}
__device__ __forceinline__ unsigned f2tf32(float v) {
    unsigned u;
    asm("cvt.rna.tf32.f32 %0, %1;" : "=r"(u) : "f"(v));
    return u;
}
__device__ __forceinline__ void mma_bf16(float* c, const unsigned* a,
                                         unsigned b0, unsigned b1) {
    asm volatile(
        "mma.sync.aligned.m16n8k16.row.col.f32.bf16.bf16.f32 "
        "{%0,%1,%2,%3}, {%4,%5,%6,%7}, {%8,%9}, {%0,%1,%2,%3};"
        : "+f"(c[0]), "+f"(c[1]), "+f"(c[2]), "+f"(c[3])
        : "r"(a[0]), "r"(a[1]), "r"(a[2]), "r"(a[3]), "r"(b0), "r"(b1));
}
__device__ __forceinline__ void mma_tf32(float* c, const unsigned* a,
                                         unsigned b0, unsigned b1) {
    asm volatile(
        "mma.sync.aligned.m16n8k8.row.col.f32.tf32.tf32.f32 "
        "{%0,%1,%2,%3}, {%4,%5,%6,%7}, {%8,%9}, {%0,%1,%2,%3};"
        : "+f"(c[0]), "+f"(c[1]), "+f"(c[2]), "+f"(c[3])
        : "r"(a[0]), "r"(a[1]), "r"(a[2]), "r"(a[3]), "r"(b0), "r"(b1));
}
__device__ __forceinline__ unsigned s2u(const void* p) {
    return (unsigned)__cvta_generic_to_shared(p);
}
__device__ __forceinline__ void cp16(unsigned dst, const void* src, bool pred) {
    int sz = pred ? 16 : 0;
    asm volatile("cp.async.cg.shared.global [%0], [%1], 16, %2;"
                 :: "r"(dst), "l"(src), "r"(sz));
}
#define CP_COMMIT() asm volatile("cp.async.commit_group;")
#define CP_WAIT1()  asm volatile("cp.async.wait_group 1;")
#define CP_WAIT0()  asm volatile("cp.async.wait_group 0;")

// ---------------- fp32 -> bf16 convert ----------------
__global__ void k_cvt(const float* __restrict__ in, __nv_bfloat16* __restrict__ out,
                      int n4) {
    int i = blockIdx.x * blockDim.x + threadIdx.x;
    if (i < n4) {
        float4 v = ((const float4*)in)[i];
        ((uint2*)out)[i] = make_uint2(pack_bf16x2(v.x, v.y), pack_bf16x2(v.z, v.w));
    }
}

// ---------------- CSR build ----------------
__global__ void k_count(const int* __restrict__ rows, int* __restrict__ deg) {
    int i = blockIdx.x * blockDim.x + threadIdx.x;
    if (i < NEDGES / 4) {
        int4 r = ((const int4*)rows)[i];
        atomicAdd(&deg[r.x], 1);
        atomicAdd(&deg[r.y], 1);
        atomicAdd(&deg[r.z], 1);
        atomicAdd(&deg[r.w], 1);
    }
}

// step 1: block-local exclusive scan (1024 elems/block) + block totals
__global__ __launch_bounds__(1024) void k_scan1(const int* __restrict__ deg,
                                                int* __restrict__ rp,
                                                int* __restrict__ blksum) {
    __shared__ int wsum[32];
    int tid = threadIdx.x, lane = tid & 31, wid = tid >> 5;
    int i = blockIdx.x * 1024 + tid;
    int v = (i < NNODES) ? deg[i] : 0;
    int x = v;
    #pragma unroll
    for (int d = 1; d < 32; d <<= 1) {
        int y = __shfl_up_sync(0xffffffffu, x, d);
        if (lane >= d) x += y;
    }
    if (lane == 31) wsum[wid] = x;
    __syncthreads();
    if (wid == 0) {
        int s = wsum[lane];
        #pragma unroll
        for (int d = 1; d < 32; d <<= 1) {
            int y = __shfl_up_sync(0xffffffffu, s, d);
            if (lane >= d) s += y;
        }
        wsum[lane] = s;
    }
    __syncthreads();
    int excl = (wid ? wsum[wid - 1] : 0) + x - v;
    if (i < NNODES) rp[i] = excl;
    if (tid == 1023) blksum[blockIdx.x] = wsum[31];
}

// step 2: scan the 98 block totals in place (exclusive)
__global__ void k_scan2(int* __restrict__ blksum) {
    __shared__ int ws[4];
    int tid = threadIdx.x, lane = tid & 31, wid = tid >> 5;   // 128 threads
    int v = (tid < SCAN_BLKS) ? blksum[tid] : 0;
    int x = v;
    #pragma unroll
    for (int d = 1; d < 32; d <<= 1) {
        int y = __shfl_up_sync(0xffffffffu, x, d);
        if (lane >= d) x += y;
    }
    if (lane == 31) ws[wid] = x;
    __syncthreads();
    int base = 0;
    for (int w = 0; w < 4; w++) {
        if (w < wid) base += ws[w];
    }
    if (tid < SCAN_BLKS) blksum[tid] = base + x - v;   // exclusive
}

// step 3: add block offsets, fill cursor, set rp[N]
__global__ void k_scan3(int* __restrict__ rp, int* __restrict__ cur,
                        const int* __restrict__ blksum) {
    int i = blockIdx.x * blockDim.x + threadIdx.x;
    if (i < NNODES) {
        int r = rp[i] + blksum[i >> 10];
        rp[i] = r;
        cur[i] = r;
    }
    if (i == 0) rp[NNODES] = NEDGES;
}

__global__ void k_fill(const int* __restrict__ rows, const int* __restrict__ cols,
                       int* __restrict__ cur, int* __restrict__ col) {
    int i = blockIdx.x * blockDim.x + threadIdx.x;
    if (i < NEDGES / 4) {
        int4 r = ((const int4*)rows)[i];
        int4 c = ((const int4*)cols)[i];
        col[atomicAdd(&cur[r.x], 1)] = c.x;
        col[atomicAdd(&cur[r.y], 1)] = c.y;
        col[atomicAdd(&cur[r.z], 1)] = c.z;
        col[atomicAdd(&cur[r.w], 1)] = c.w;
    }
}

// ---------------- pipelined bf16 GEMM (outputs fp16: s | z) ----------------
#define PITCH 80
__global__ __launch_bounds__(256) void k_gemm_bf16(
    const __nv_bfloat16* __restrict__ A, int K,
    const __nv_bfloat16* __restrict__ W,
    __half* __restrict__ Csh, __half* __restrict__ Czh)
{
    __shared__ __align__(16) unsigned char smA[2][128 * PITCH];
    __shared__ __align__(16) unsigned char smB[2][128 * PITCH];
    const int tid = threadIdx.x, lane = tid & 31, wid = tid >> 5;
    const int warpM = wid & 3, warpN = wid >> 2;
    const int row0 = blockIdx.x * 128;
    const int ldw = 2 * K;
    const __nv_bfloat16* Wb = W + (size_t)blockIdx.y * K;
    __half* C = blockIdx.y ? Czh : Csh;
    const int NT = K >> 5;

    const int lr0 = tid >> 2, lc0 = tid & 3;
    const int lr1 = (tid + 256) >> 2, lc1 = lc0;
    const bool p0 = (row0 + lr0) < NNODES;
    const bool p1 = (row0 + lr1) < NNODES;

    float acc[2][8][4];
    #pragma unroll
    for (int mi = 0; mi < 2; mi++)
        #pragma unroll
        for (int ni = 0; ni < 8; ni++)
            #pragma unroll
            for (int q = 0; q < 4; q++) acc[mi][ni][q] = 0.f;

    {
        cp16(s2u(smA[0] + lr0 * PITCH + lc0 * 16),
             A + (size_t)(row0 + lr0) * K + lc0 * 8, p0);
        cp16(s2u(smA[0] + lr1 * PITCH + lc1 * 16),
             A + (size_t)(row0 + lr1) * K + lc1 * 8, p1);
        cp16(s2u(smB[0] + lr0 * PITCH + lc0 * 16),
             Wb + (size_t)lr0 * ldw + lc0 * 8, true);
        cp16(s2u(smB[0] + lr1 * PITCH + lc1 * 16),
             Wb + (size_t)lr1 * ldw + lc1 * 8, true);
        CP_COMMIT();
    }

    for (int kt = 0; kt < NT; kt++) {
        if (kt + 1 < NT) {
            int k0 = (kt + 1) << 5;
            int nb = (kt + 1) & 1;
            cp16(s2u(smA[nb] + lr0 * PITCH + lc0 * 16),
                 A + (size_t)(row0 + lr0) * K + k0 + lc0 * 8, p0);
            cp16(s2u(smA[nb] + lr1 * PITCH + lc1 * 16),
                 A + (size_t)(row0 + lr1) * K + k0 + lc1 * 8, p1);
            cp16(s2u(smB[nb] + lr0 * PITCH + lc0 * 16),
                 Wb + (size_t)lr0 * ldw + k0 + lc0 * 8, true);
            cp16(s2u(smB[nb] + lr1 * PITCH + lc1 * 16),
                 Wb + (size_t)lr1 * ldw + k0 + lc1 * 8, true);
            CP_COMMIT();
            CP_WAIT1();
        } else {
            CP_WAIT0();
        }
        __syncthreads();

        const unsigned char* Ab = smA[kt & 1];
        const unsigned char* Bb = smB[kt & 1];
        #pragma unroll
        for (int ks = 0; ks < 2; ks++) {
            const int q0 = ks * 8 + (lane & 3);
            unsigned af[2][4];
            #pragma unroll
            for (int mi = 0; mi < 2; mi++) {
                int r = warpM * 32 + mi * 16 + (lane >> 2);
                af[mi][0] = *(const unsigned*)(Ab + r * PITCH + q0 * 4);
                af[mi][1] = *(const unsigned*)(Ab + (r + 8) * PITCH + q0 * 4);
                af[mi][2] = *(const unsigned*)(Ab + r * PITCH + (q0 + 4) * 4);
                af[mi][3] = *(const unsigned*)(Ab + (r + 8) * PITCH + (q0 + 4) * 4);
            }
            #pragma unroll
            for (int ni = 0; ni < 8; ni++) {
                int n = warpN * 64 + ni * 8 + (lane >> 2);
                unsigned b0 = *(const unsigned*)(Bb + n * PITCH + q0 * 4);
                unsigned b1 = *(const unsigned*)(Bb + n * PITCH + (q0 + 4) * 4);
                mma_bf16(acc[0][ni], af[0], b0, b1);
                mma_bf16(acc[1][ni], af[1], b0, b1);
            }
        }
        __syncthreads();
    }

    #pragma unroll
    for (int mi = 0; mi < 2; mi++) {
        int rbase = row0 + warpM * 32 + mi * 16 + (lane >> 2);
        #pragma unroll
        for (int ni = 0; ni < 8; ni++) {
            int col = warpN * 64 + ni * 8 + 2 * (lane & 3);
            if (rbase < NNODES)
                *(__half2*)(C + (size_t)rbase * NHID + col) =
                    __floats2half2_rn(acc[mi][ni][0], acc[mi][ni][1]);
            if (rbase + 8 < NNODES)
                *(__half2*)(C + (size_t)(rbase + 8) * NHID + col) =
                    __floats2half2_rn(acc[mi][ni][2], acc[mi][ni][3]);
        }
    }
}

// ---------------- SpMM: h = relu(s + (A@z)/(deg+1)) ----------------
__global__ __launch_bounds__(256) void k_spmm(const __half* __restrict__ zh,
                                              const __half* __restrict__ sh,
                                              const int* __restrict__ rp,
                                              const int* __restrict__ col,
                                              __nv_bfloat16* __restrict__ hb) {
    int lane = threadIdx.x & 31;
    int n    = (blockIdx.x * 256 + threadIdx.x) >> 5;
    if (n >= NNODES) return;
    int e = rp[n], end = rp[n + 1];
    int deg = end - e;
    float ax = 0.f, ay = 0.f, az = 0.f, aw = 0.f;
    for (; e + 4 <= end; e += 4) {
        int c0 = col[e], c1 = col[e + 1], c2 = col[e + 2], c3 = col[e + 3];
        uint2 u0 = *(const uint2*)(zh + (size_t)c0 * NHID + lane * 4);
        uint2 u1 = *(const uint2*)(zh + (size_t)c1 * NHID + lane * 4);
        uint2 u2 = *(const uint2*)(zh + (size_t)c2 * NHID + lane * 4);
        uint2 u3 = *(const uint2*)(zh + (size_t)c3 * NHID + lane * 4);
        float2 a0 = __half22float2(*(__half2*)&u0.x), a1 = __half22float2(*(__half2*)&u0.y);
        float2 b0 = __half22float2(*(__half2*)&u1.x), b1 = __half22float2(*(__half2*)&u1.y);
        float2 d0 = __half22float2(*(__half2*)&u2.x), d1 = __half22float2(*(__half2*)&u2.y);
        float2 e0 = __half22float2(*(__half2*)&u3.x), e1 = __half22float2(*(__half2*)&u3.y);
        ax += (a0.x + b0.x) + (d0.x + e0.x);
        ay += (a0.y + b0.y) + (d0.y + e0.y);
        az += (a1.x + b1.x) + (d1.x + e1.x);
        aw += (a1.y + b1.y) + (d1.y + e1.y);
    }
    for (; e < end; e++) {
        int c0 = col[e];
        uint2 u0 = *(const uint2*)(zh + (size_t)c0 * NHID + lane * 4);
        float2 a0 = __half22float2(*(__half2*)&u0.x), a1 = __half22float2(*(__half2*)&u0.y);
        ax += a0.x; ay += a0.y; az += a1.x; aw += a1.y;
    }
    float inv = 1.0f / (1.0f + (float)deg);
    uint2 su = *(const uint2*)(sh + (size_t)n * NHID + lane * 4);
    float2 s0 = __half22float2(*(__half2*)&su.x);
    float2 s1 = __half22float2(*(__half2*)&su.y);
    float ox = fmaxf(fmaf(ax, inv, s0.x), 0.f);
    float oy = fmaxf(fmaf(ay, inv, s0.y), 0.f);
    float oz = fmaxf(fmaf(az, inv, s1.x), 0.f);
    float ow = fmaxf(fmaf(aw, inv, s1.y), 0.f);
    *(uint2*)(hb + (size_t)n * NHID + lane * 4) =
        make_uint2(pack_bf16x2(ox, oy), pack_bf16x2(oz, ow));
}

// ---------------- MLP + log_softmax (tf32 MMA; A from bf16 h) ----------------
__global__ __launch_bounds__(128) void k_mlp_tc(const __nv_bfloat16* __restrict__ hb,
                                                const float* __restrict__ Wm,
                                                const float* __restrict__ b,
                                                float* __restrict__ out) {
    __shared__ unsigned As[32][132];
    __shared__ unsigned Bsm[NCLASS][132];
    __shared__ float    Ls[128][41];
    __shared__ float    bs[NCLASS];

    const int tid = threadIdx.x, lane = tid & 31, wid = tid >> 5;
    const int row0 = blockIdx.x * 128;

    for (int i = tid; i < NCLASS * NHID; i += 128)
        Bsm[i >> 7][i & 127] = f2tf32(Wm[i]);
    if (tid < NCLASS) bs[tid] = b[tid];

    float acc[2][5][4];
    #pragma unroll
    for (int mi = 0; mi < 2; mi++)
        #pragma unroll
        for (int ni = 0; ni < 5; ni++)
            #pragma unroll
            for (int q = 0; q < 4; q++) acc[mi][ni][q] = 0.f;

    for (int k0 = 0; k0 < NHID; k0 += 32) {
        #pragma unroll
        for (int j = 0; j < 8; j++) {
            int i  = tid + j * 128;
            int r  = i >> 3;
            int c4 = (i & 7) * 4;
            uint2 u = make_uint2(0u, 0u);
            if (row0 + r < NNODES)
                u = *(const uint2*)(hb + (size_t)(row0 + r) * NHID + k0 + c4);
            As[c4 + 0][r] = u.x << 16;
            As[c4 + 1][r] = u.x & 0xffff0000u;
            As[c4 + 2][r] = u.y << 16;
            As[c4 + 3][r] = u.y & 0xffff0000u;
        }
        __syncthreads();

        #pragma unroll
        for (int kk = 0; kk < 32; kk += 8) {
            const int kc = kk + (lane & 3);
            unsigned af[2][4];
            #pragma unroll
            for (int mi = 0; mi < 2; mi++) {
                int r = wid * 32 + mi * 16 + (lane >> 2);
                af[mi][0] = As[kc][r];
                af[mi][1] = As[kc][r + 8];
                af[mi][2] = As[kc + 4][r];
                af[mi][3] = As[kc + 4][r + 8];
            }
            #pragma unroll
            for (int ni = 0; ni < 5; ni++) {
                int n = ni * 8 + (lane >> 2);
                unsigned b0 = Bsm[n][k0 + kc];
                unsigned b1 = Bsm[n][k0 + kc + 4];
                mma_tf32(acc[0][ni], af[0], b0, b1);
                mma_tf32(acc[1][ni], af[1], b0, b1);
            }
        }
        __syncthreads();
    }

    #pragma unroll
    for (int mi = 0; mi < 2; mi++) {
        int r = wid * 32 + mi * 16 + (lane >> 2);
        #pragma unroll
        for (int ni = 0; ni < 5; ni++) {
            int c = ni * 8 + 2 * (lane & 3);
            Ls[r][c]         = acc[mi][ni][0];
            Ls[r][c + 1]     = acc[mi][ni][1];
            Ls[r + 8][c]     = acc[mi][ni][2];
            Ls[r + 8][c + 1] = acc[mi][ni][3];
        }
    }
    __syncthreads();

    int gr = row0 + tid;
    if (gr >= NNODES) return;
    float l[NCLASS];
    float m = -INFINITY;
    #pragma unroll
    for (int c = 0; c < NCLASS; c++) {
        l[c] = Ls[tid][c] + bs[c];
        m = fmaxf(m, l[c]);
    }
    float se = 0.f;
    #pragma unroll
    for (int c = 0; c < NCLASS; c++) se += expf(l[c] - m);
    float lse = m + logf(se);
    float* op = out + (size_t)gr * NCLASS;
    #pragma unroll
    for (int c = 0; c < NCLASS; c += 4)
        *(float4*)(op + c) = make_float4(l[c] - lse, l[c + 1] - lse,
                                         l[c + 2] - lse, l[c + 3] - lse);
}

// ---------------- launch ----------------
extern "C" void kernel_launch(void* const* d_in, const int* in_sizes, int n_in,
                              void* d_out, int out_size) {
    const float* x    = (const float*)d_in[0];
    const float* W1   = (const float*)d_in[1];
    const float* W2   = (const float*)d_in[2];
    const float* mW   = (const float*)d_in[3];
    const float* mb   = (const float*)d_in[4];
    const int*   rows = (const int*)d_in[5];
    const int*   cols = (const int*)d_in[6];
    float*       out  = (float*)d_out;

    __half *p_sh, *p_zh;
    __nv_bfloat16 *p_hb, *p_xb, *p_w1b, *p_w2b;
    int *p_deg, *p_rp, *p_cur, *p_col, *p_bs;
    cudaGetSymbolAddress((void**)&p_sh,  g_sh);
    cudaGetSymbolAddress((void**)&p_zh,  g_zh);
    cudaGetSymbolAddress((void**)&p_hb,  g_hb);
    cudaGetSymbolAddress((void**)&p_xb,  g_xb);
    cudaGetSymbolAddress((void**)&p_w1b, g_w1b);
    cudaGetSymbolAddress((void**)&p_w2b, g_w2b);
    cudaGetSymbolAddress((void**)&p_deg, g_deg);
    cudaGetSymbolAddress((void**)&p_rp,  g_rowptr);
    cudaGetSymbolAddress((void**)&p_cur, g_cursor);
    cudaGetSymbolAddress((void**)&p_col, g_col);
    cudaGetSymbolAddress((void**)&p_bs,  g_blksum);

    static cudaStream_t s_side = nullptr;
    static cudaEvent_t  ev_fork = nullptr, ev_join = nullptr;
    if (s_side == nullptr) {
        cudaStreamCreate(&s_side);
        cudaEventCreateWithFlags(&ev_fork, cudaEventDisableTiming);
        cudaEventCreateWithFlags(&ev_join, cudaEventDisableTiming);
    }

    const int GB_E4 = (NEDGES / 4 + 255) / 256;
    const int GB_W  = (NNODES * 32 + 255) / 256;
    const int GB_T  = (NNODES + 127) / 128;
    const int GB_N  = (NNODES + 255) / 256;
    const dim3 GB_G(GB_T, 2);
    const int n4x  = NNODES * NFEAT / 4;
    const int n4w1 = NHID * 2 * NFEAT / 4;
    const int n4w2 = NHID * 2 * NHID / 4;

    // ---- fork: CSR build on side stream (multi-block scan) ----
    cudaEventRecord(ev_fork, 0);
    cudaStreamWaitEvent(s_side, ev_fork, 0);
    cudaMemsetAsync(p_deg, 0, NNODES * sizeof(int), s_side);
    k_count<<<GB_E4, 256, 0, s_side>>>(rows, p_deg);
    k_scan1<<<SCAN_BLKS, 1024, 0, s_side>>>(p_deg, p_rp, p_bs);
    k_scan2<<<1, 128, 0, s_side>>>(p_bs);
    k_scan3<<<GB_N, 256, 0, s_side>>>(p_rp, p_cur, p_bs);
    k_fill<<<GB_E4, 256, 0, s_side>>>(rows, cols, p_cur, p_col);
    cudaEventRecord(ev_join, s_side);

    // ---- main: bf16 conversions + layer-1 GEMM (R10 shape) ----
    k_cvt<<<(n4w1 + 255) / 256, 256>>>(W1, p_w1b, n4w1);
    k_cvt<<<(n4w2 + 255) / 256, 256>>>(W2, p_w2b, n4w2);
    k_cvt<<<(n4x + 255) / 256, 256>>>(x,  p_xb,  n4x);
    k_gemm_bf16<<<GB_G, 256>>>(p_xb, NFEAT, p_w1b, p_sh, p_zh);

    // ---- join: SpMM needs CSR + z + s ----
    cudaStreamWaitEvent(0, ev_join, 0);
    k_spmm<<<GB_W, 256>>>(p_zh, p_sh, p_rp, p_col, p_hb);

    // Layer 2
    k_gemm_bf16<<<GB_G, 256>>>(p_hb, NHID, p_w2b, p_sh, p_zh);
    k_spmm<<<GB_W, 256>>>(p_zh, p_sh, p_rp, p_col, p_hb);

    // MLP + log_softmax
    k_mlp_tc<<<GB_T, 128>>>(p_hb, mW, mb, out);
}

// round 17
// speedup vs baseline: 1.1966x; 1.0282x over previous
#include <cuda_runtime.h>
#include <cuda_fp16.h>
#include <cuda_bf16.h>
#include <math.h>

#define NNODES 100000
#define NEDGES 3200000
#define NFEAT  256
#define NHID   128
#define NCLASS 40
#define SCAN_BLKS ((NNODES + 1023) / 1024)   // 98

// ---------------- scratch (static device globals; no allocs) ----------------
__device__ __half         g_sh[(size_t)NNODES * NHID];   // self proj fp16
__device__ __half         g_zh[(size_t)NNODES * NHID];   // neigh proj fp16
__device__ __nv_bfloat16  g_hb[(size_t)NNODES * NHID];   // layer output bf16
__device__ __nv_bfloat16  g_xb[(size_t)NNODES * NFEAT];  // x in bf16
__device__ __nv_bfloat16  g_w1b[NHID * 2 * NFEAT];
__device__ __nv_bfloat16  g_w2b[NHID * 2 * NHID];
__device__ int            g_deg[NNODES];
__device__ int            g_rowptr[NNODES + 1];
__device__ int            g_cursor[NNODES];
__device__ int            g_col[NEDGES];
__device__ int            g_blksum[SCAN_BLKS];

// ---------------- helpers ----------------
__device__ __forceinline__ unsigned pack_bf16x2(float lo, float hi) {
    unsigned u;
    asm("cvt.rn.bf16x2.f32 %0, %1, %2;" : "=r"(u) : "f"(hi), "f"(lo));
    return u;
}
__device__ __forceinline__ unsigned f2tf32(float v) {
    unsigned u;
    asm("cvt.rna.tf32.f32 %0, %1;" : "=r"(u) : "f"(v));
    return u;
}
__device__ __forceinline__ void mma_bf16(float* c, const unsigned* a,
                                         unsigned b0, unsigned b1) {
    asm volatile(
        "mma.sync.aligned.m16n8k16.row.col.f32.bf16.bf16.f32 "
        "{%0,%1,%2,%3}, {%4,%5,%6,%7}, {%8,%9}, {%0,%1,%2,%3};"
        : "+f"(c[0]), "+f"(c[1]), "+f"(c[2]), "+f"(c[3])
        : "r"(a[0]), "r"(a[1]), "r"(a[2]), "r"(a[3]), "r"(b0), "r"(b1));
}
__device__ __forceinline__ void mma_tf32(float* c, const unsigned* a,
                                         unsigned b0, unsigned b1) {
    asm volatile(
        "mma.sync.aligned.m16n8k8.row.col.f32.tf32.tf32.f32 "
        "{%0,%1,%2,%3}, {%4,%5,%6,%7}, {%8,%9}, {%0,%1,%2,%3};"
        : "+f"(c[0]), "+f"(c[1]), "+f"(c[2]), "+f"(c[3])
        : "r"(a[0]), "r"(a[1]), "r"(a[2]), "r"(a[3]), "r"(b0), "r"(b1));
}
__device__ __forceinline__ unsigned s2u(const void* p) {
    return (unsigned)__cvta_generic_to_shared(p);
}
__device__ __forceinline__ void cp16(unsigned dst, const void* src, bool pred) {
    int sz = pred ? 16 : 0;
    asm volatile("cp.async.cg.shared.global [%0], [%1], 16, %2;"
                 :: "r"(dst), "l"(src), "r"(sz));
}
#define CP_COMMIT() asm volatile("cp.async.commit_group;")
#define CP_WAIT1()  asm volatile("cp.async.wait_group 1;")
#define CP_WAIT0()  asm volatile("cp.async.wait_group 0;")

// ---------------- fp32 -> bf16 convert ----------------
__global__ void k_cvt(const float* __restrict__ in, __nv_bfloat16* __restrict__ out,
                      int n4) {
    int i = blockIdx.x * blockDim.x + threadIdx.x;
    if (i < n4) {
        float4 v = ((const float4*)in)[i];
        ((uint2*)out)[i] = make_uint2(pack_bf16x2(v.x, v.y), pack_bf16x2(v.z, v.w));
    }
}

// ---------------- CSR build ----------------
__global__ void k_count(const int* __restrict__ rows, int* __restrict__ deg) {
    int i = blockIdx.x * blockDim.x + threadIdx.x;
    if (i < NEDGES / 4) {
        int4 r = ((const int4*)rows)[i];
        atomicAdd(&deg[r.x], 1);
        atomicAdd(&deg[r.y], 1);
        atomicAdd(&deg[r.z], 1);
        atomicAdd(&deg[r.w], 1);
    }
}

__global__ __launch_bounds__(1024) void k_scan1(const int* __restrict__ deg,
                                                int* __restrict__ rp,
                                                int* __restrict__ blksum) {
    __shared__ int wsum[32];
    int tid = threadIdx.x, lane = tid & 31, wid = tid >> 5;
    int i = blockIdx.x * 1024 + tid;
    int v = (i < NNODES) ? deg[i] : 0;
    int x = v;
    #pragma unroll
    for (int d = 1; d < 32; d <<= 1) {
        int y = __shfl_up_sync(0xffffffffu, x, d);
        if (lane >= d) x += y;
    }
    if (lane == 31) wsum[wid] = x;
    __syncthreads();
    if (wid == 0) {
        int s = wsum[lane];
        #pragma unroll
        for (int d = 1; d < 32; d <<= 1) {
            int y = __shfl_up_sync(0xffffffffu, s, d);
            if (lane >= d) s += y;
        }
        wsum[lane] = s;
    }
    __syncthreads();
    int excl = (wid ? wsum[wid - 1] : 0) + x - v;
    if (i < NNODES) rp[i] = excl;
    if (tid == 1023) blksum[blockIdx.x] = wsum[31];
}

__global__ void k_scan2(int* __restrict__ blksum) {
    __shared__ int ws[4];
    int tid = threadIdx.x, lane = tid & 31, wid = tid >> 5;
    int v = (tid < SCAN_BLKS) ? blksum[tid] : 0;
    int x = v;
    #pragma unroll
    for (int d = 1; d < 32; d <<= 1) {
        int y = __shfl_up_sync(0xffffffffu, x, d);
        if (lane >= d) x += y;
    }
    if (lane == 31) ws[wid] = x;
    __syncthreads();
    int base = 0;
    for (int w = 0; w < 4; w++) {
        if (w < wid) base += ws[w];
    }
    if (tid < SCAN_BLKS) blksum[tid] = base + x - v;
}

__global__ void k_scan3(int* __restrict__ rp, int* __restrict__ cur,
                        const int* __restrict__ blksum) {
    int i = blockIdx.x * blockDim.x + threadIdx.x;
    if (i < NNODES) {
        int r = rp[i] + blksum[i >> 10];
        rp[i] = r;
        cur[i] = r;
    }
    if (i == 0) rp[NNODES] = NEDGES;
}

__global__ void k_fill(const int* __restrict__ rows, const int* __restrict__ cols,
                       int* __restrict__ cur, int* __restrict__ col) {
    int i = blockIdx.x * blockDim.x + threadIdx.x;
    if (i < NEDGES / 4) {
        int4 r = ((const int4*)rows)[i];
        int4 c = ((const int4*)cols)[i];
        col[atomicAdd(&cur[r.x], 1)] = c.x;
        col[atomicAdd(&cur[r.y], 1)] = c.y;
        col[atomicAdd(&cur[r.z], 1)] = c.z;
        col[atomicAdd(&cur[r.w], 1)] = c.w;
    }
}

// ---------------- pipelined bf16 GEMM (outputs fp16: s | z) ----------------
#define PITCH 80
__global__ __launch_bounds__(256) void k_gemm_bf16(
    const __nv_bfloat16* __restrict__ A, int K,
    const __nv_bfloat16* __restrict__ W,
    __half* __restrict__ Csh, __half* __restrict__ Czh)
{
    __shared__ __align__(16) unsigned char smA[2][128 * PITCH];
    __shared__ __align__(16) unsigned char smB[2][128 * PITCH];
    const int tid = threadIdx.x, lane = tid & 31, wid = tid >> 5;
    const int warpM = wid & 3, warpN = wid >> 2;
    const int row0 = blockIdx.x * 128;
    const int ldw = 2 * K;
    const __nv_bfloat16* Wb = W + (size_t)blockIdx.y * K;
    __half* C = blockIdx.y ? Czh : Csh;
    const int NT = K >> 5;

    const int lr0 = tid >> 2, lc0 = tid & 3;
    const int lr1 = (tid + 256) >> 2, lc1 = lc0;
    const bool p0 = (row0 + lr0) < NNODES;
    const bool p1 = (row0 + lr1) < NNODES;

    float acc[2][8][4];
    #pragma unroll
    for (int mi = 0; mi < 2; mi++)
        #pragma unroll
        for (int ni = 0; ni < 8; ni++)
            #pragma unroll
            for (int q = 0; q < 4; q++) acc[mi][ni][q] = 0.f;

    {
        cp16(s2u(smA[0] + lr0 * PITCH + lc0 * 16),
             A + (size_t)(row0 + lr0) * K + lc0 * 8, p0);
        cp16(s2u(smA[0] + lr1 * PITCH + lc1 * 16),
             A + (size_t)(row0 + lr1) * K + lc1 * 8, p1);
        cp16(s2u(smB[0] + lr0 * PITCH + lc0 * 16),
             Wb + (size_t)lr0 * ldw + lc0 * 8, true);
        cp16(s2u(smB[0] + lr1 * PITCH + lc1 * 16),
             Wb + (size_t)lr1 * ldw + lc1 * 8, true);
        CP_COMMIT();
    }

    for (int kt = 0; kt < NT; kt++) {
        if (kt + 1 < NT) {
            int k0 = (kt + 1) << 5;
            int nb = (kt + 1) & 1;
            cp16(s2u(smA[nb] + lr0 * PITCH + lc0 * 16),
                 A + (size_t)(row0 + lr0) * K + k0 + lc0 * 8, p0);
            cp16(s2u(smA[nb] + lr1 * PITCH + lc1 * 16),
                 A + (size_t)(row0 + lr1) * K + k0 + lc1 * 8, p1);
            cp16(s2u(smB[nb] + lr0 * PITCH + lc0 * 16),
                 Wb + (size_t)lr0 * ldw + k0 + lc0 * 8, true);
            cp16(s2u(smB[nb] + lr1 * PITCH + lc1 * 16),
                 Wb + (size_t)lr1 * ldw + k0 + lc1 * 8, true);
            CP_COMMIT();
            CP_WAIT1();
        } else {
            CP_WAIT0();
        }
        __syncthreads();

        const unsigned char* Ab = smA[kt & 1];
        const unsigned char* Bb = smB[kt & 1];
        #pragma unroll
        for (int ks = 0; ks < 2; ks++) {
            const int q0 = ks * 8 + (lane & 3);
            unsigned af[2][4];
            #pragma unroll
            for (int mi = 0; mi < 2; mi++) {
                int r = warpM * 32 + mi * 16 + (lane >> 2);
                af[mi][0] = *(const unsigned*)(Ab + r * PITCH + q0 * 4);
                af[mi][1] = *(const unsigned*)(Ab + (r + 8) * PITCH + q0 * 4);
                af[mi][2] = *(const unsigned*)(Ab + r * PITCH + (q0 + 4) * 4);
                af[mi][3] = *(const unsigned*)(Ab + (r + 8) * PITCH + (q0 + 4) * 4);
            }
            #pragma unroll
            for (int ni = 0; ni < 8; ni++) {
                int n = warpN * 64 + ni * 8 + (lane >> 2);
                unsigned b0 = *(const unsigned*)(Bb + n * PITCH + q0 * 4);
                unsigned b1 = *(const unsigned*)(Bb + n * PITCH + (q0 + 4) * 4);
                mma_bf16(acc[0][ni], af[0], b0, b1);
                mma_bf16(acc[1][ni], af[1], b0, b1);
            }
        }
        __syncthreads();
    }

    #pragma unroll
    for (int mi = 0; mi < 2; mi++) {
        int rbase = row0 + warpM * 32 + mi * 16 + (lane >> 2);
        #pragma unroll
        for (int ni = 0; ni < 8; ni++) {
            int col = warpN * 64 + ni * 8 + 2 * (lane & 3);
            if (rbase < NNODES)
                *(__half2*)(C + (size_t)rbase * NHID + col) =
                    __floats2half2_rn(acc[mi][ni][0], acc[mi][ni][1]);
            if (rbase + 8 < NNODES)
                *(__half2*)(C + (size_t)(rbase + 8) * NHID + col) =
                    __floats2half2_rn(acc[mi][ni][2], acc[mi][ni][3]);
        }
    }
}

// ---------------- SpMM: half-warp-per-edge uint4 gathers ----------------
// Warp = one node. Lanes 0-15 handle even edge, 16-31 odd edge; each lane
// loads uint4 (8 cols). shfl_xor(16) merges halves; lanes 0-15 do epilogue.
__global__ __launch_bounds__(256) void k_spmm(const __half* __restrict__ zh,
                                              const __half* __restrict__ sh,
                                              const int* __restrict__ rp,
                                              const int* __restrict__ col,
                                              __nv_bfloat16* __restrict__ hb) {
    int lane = threadIdx.x & 31;
    int n    = (blockIdx.x * 256 + threadIdx.x) >> 5;
    if (n >= NNODES) return;
    int e = rp[n], end = rp[n + 1];
    int deg = end - e;
    int half = lane >> 4;          // 0 or 1
    int li   = lane & 15;          // lane within half: 8 cols each

    float a0 = 0.f, a1 = 0.f, a2 = 0.f, a3 = 0.f;
    float a4 = 0.f, a5 = 0.f, a6 = 0.f, a7 = 0.f;

    for (; e + 2 <= end; e += 2) {
        int c = col[e + half];
        uint4 u = *(const uint4*)(zh + (size_t)c * NHID + li * 8);
        float2 p0 = __half22float2(*(__half2*)&u.x);
        float2 p1 = __half22float2(*(__half2*)&u.y);
        float2 p2 = __half22float2(*(__half2*)&u.z);
        float2 p3 = __half22float2(*(__half2*)&u.w);
        a0 += p0.x; a1 += p0.y; a2 += p1.x; a3 += p1.y;
        a4 += p2.x; a5 += p2.y; a6 += p3.x; a7 += p3.y;
    }
    if (e < end && half == 0) {    // odd tail: lower half only
        int c = col[e];
        uint4 u = *(const uint4*)(zh + (size_t)c * NHID + li * 8);
        float2 p0 = __half22float2(*(__half2*)&u.x);
        float2 p1 = __half22float2(*(__half2*)&u.y);
        float2 p2 = __half22float2(*(__half2*)&u.z);
        float2 p3 = __half22float2(*(__half2*)&u.w);
        a0 += p0.x; a1 += p0.y; a2 += p1.x; a3 += p1.y;
        a4 += p2.x; a5 += p2.y; a6 += p3.x; a7 += p3.y;
    }

    // merge halves (xor -> both halves get total; use lower half)
    a0 += __shfl_xor_sync(0xffffffffu, a0, 16);
    a1 += __shfl_xor_sync(0xffffffffu, a1, 16);
    a2 += __shfl_xor_sync(0xffffffffu, a2, 16);
    a3 += __shfl_xor_sync(0xffffffffu, a3, 16);
    a4 += __shfl_xor_sync(0xffffffffu, a4, 16);
    a5 += __shfl_xor_sync(0xffffffffu, a5, 16);
    a6 += __shfl_xor_sync(0xffffffffu, a6, 16);
    a7 += __shfl_xor_sync(0xffffffffu, a7, 16);

    if (half == 0) {
        float inv = 1.0f / (1.0f + (float)deg);
        uint4 su = *(const uint4*)(sh + (size_t)n * NHID + li * 8);
        float2 s0 = __half22float2(*(__half2*)&su.x);
        float2 s1 = __half22float2(*(__half2*)&su.y);
        float2 s2 = __half22float2(*(__half2*)&su.z);
        float2 s3 = __half22float2(*(__half2*)&su.w);
        float o0 = fmaxf(fmaf(a0, inv, s0.x), 0.f);
        float o1 = fmaxf(fmaf(a1, inv, s0.y), 0.f);
        float o2 = fmaxf(fmaf(a2, inv, s1.x), 0.f);
        float o3 = fmaxf(fmaf(a3, inv, s1.y), 0.f);
        float o4 = fmaxf(fmaf(a4, inv, s2.x), 0.f);
        float o5 = fmaxf(fmaf(a5, inv, s2.y), 0.f);
        float o6 = fmaxf(fmaf(a6, inv, s3.x), 0.f);
        float o7 = fmaxf(fmaf(a7, inv, s3.y), 0.f);
        uint4 ov;
        ov.x = pack_bf16x2(o0, o1);
        ov.y = pack_bf16x2(o2, o3);
        ov.z = pack_bf16x2(o4, o5);
        ov.w = pack_bf16x2(o6, o7);
        *(uint4*)(hb + (size_t)n * NHID + li * 8) = ov;
    }
}

// ---------------- MLP + log_softmax (tf32 MMA; A from bf16 h) ----------------
__global__ __launch_bounds__(128) void k_mlp_tc(const __nv_bfloat16* __restrict__ hb,
                                                const float* __restrict__ Wm,
                                                const float* __restrict__ b,
                                                float* __restrict__ out) {
    __shared__ unsigned As[32][132];
    __shared__ unsigned Bsm[NCLASS][132];
    __shared__ float    Ls[128][41];
    __shared__ float    bs[NCLASS];

    const int tid = threadIdx.x, lane = tid & 31, wid = tid >> 5;
    const int row0 = blockIdx.x * 128;

    for (int i = tid; i < NCLASS * NHID; i += 128)
        Bsm[i >> 7][i & 127] = f2tf32(Wm[i]);
    if (tid < NCLASS) bs[tid] = b[tid];

    float acc[2][5][4];
    #pragma unroll
    for (int mi = 0; mi < 2; mi++)
        #pragma unroll
        for (int ni = 0; ni < 5; ni++)
            #pragma unroll
            for (int q = 0; q < 4; q++) acc[mi][ni][q] = 0.f;

    for (int k0 = 0; k0 < NHID; k0 += 32) {
        #pragma unroll
        for (int j = 0; j < 8; j++) {
            int i  = tid + j * 128;
            int r  = i >> 3;
            int c4 = (i & 7) * 4;
            uint2 u = make_uint2(0u, 0u);
            if (row0 + r < NNODES)
                u = *(const uint2*)(hb + (size_t)(row0 + r) * NHID + k0 + c4);
            As[c4 + 0][r] = u.x << 16;
            As[c4 + 1][r] = u.x & 0xffff0000u;
            As[c4 + 2][r] = u.y << 16;
            As[c4 + 3][r] = u.y & 0xffff0000u;
        }
        __syncthreads();

        #pragma unroll
        for (int kk = 0; kk < 32; kk += 8) {
            const int kc = kk + (lane & 3);
            unsigned af[2][4];
            #pragma unroll
            for (int mi = 0; mi < 2; mi++) {
                int r = wid * 32 + mi * 16 + (lane >> 2);
                af[mi][0] = As[kc][r];
                af[mi][1] = As[kc][r + 8];
                af[mi][2] = As[kc + 4][r];
                af[mi][3] = As[kc + 4][r + 8];
            }
            #pragma unroll
            for (int ni = 0; ni < 5; ni++) {
                int n = ni * 8 + (lane >> 2);
                unsigned b0 = Bsm[n][k0 + kc];
                unsigned b1 = Bsm[n][k0 + kc + 4];
                mma_tf32(acc[0][ni], af[0], b0, b1);
                mma_tf32(acc[1][ni], af[1], b0, b1);
            }
        }
        __syncthreads();
    }

    #pragma unroll
    for (int mi = 0; mi < 2; mi++) {
        int r = wid * 32 + mi * 16 + (lane >> 2);
        #pragma unroll
        for (int ni = 0; ni < 5; ni++) {
            int c = ni * 8 + 2 * (lane & 3);
            Ls[r][c]         = acc[mi][ni][0];
            Ls[r][c + 1]     = acc[mi][ni][1];
            Ls[r + 8][c]     = acc[mi][ni][2];
            Ls[r + 8][c + 1] = acc[mi][ni][3];
        }
    }
    __syncthreads();

    int gr = row0 + tid;
    if (gr >= NNODES) return;
    float l[NCLASS];
    float m = -INFINITY;
    #pragma unroll
    for (int c = 0; c < NCLASS; c++) {
        l[c] = Ls[tid][c] + bs[c];
        m = fmaxf(m, l[c]);
    }
    float se = 0.f;
    #pragma unroll
    for (int c = 0; c < NCLASS; c++) se += expf(l[c] - m);
    float lse = m + logf(se);
    float* op = out + (size_t)gr * NCLASS;
    #pragma unroll
    for (int c = 0; c < NCLASS; c += 4)
        *(float4*)(op + c) = make_float4(l[c] - lse, l[c + 1] - lse,
                                         l[c + 2] - lse, l[c + 3] - lse);
}

// ---------------- launch ----------------
extern "C" void kernel_launch(void* const* d_in, const int* in_sizes, int n_in,
                              void* d_out, int out_size) {
    const float* x    = (const float*)d_in[0];
    const float* W1   = (const float*)d_in[1];
    const float* W2   = (const float*)d_in[2];
    const float* mW   = (const float*)d_in[3];
    const float* mb   = (const float*)d_in[4];
    const int*   rows = (const int*)d_in[5];
    const int*   cols = (const int*)d_in[6];
    float*       out  = (float*)d_out;

    __half *p_sh, *p_zh;
    __nv_bfloat16 *p_hb, *p_xb, *p_w1b, *p_w2b;
    int *p_deg, *p_rp, *p_cur, *p_col, *p_bs;
    cudaGetSymbolAddress((void**)&p_sh,  g_sh);
    cudaGetSymbolAddress((void**)&p_zh,  g_zh);
    cudaGetSymbolAddress((void**)&p_hb,  g_hb);
    cudaGetSymbolAddress((void**)&p_xb,  g_xb);
    cudaGetSymbolAddress((void**)&p_w1b, g_w1b);
    cudaGetSymbolAddress((void**)&p_w2b, g_w2b);
    cudaGetSymbolAddress((void**)&p_deg, g_deg);
    cudaGetSymbolAddress((void**)&p_rp,  g_rowptr);
    cudaGetSymbolAddress((void**)&p_cur, g_cursor);
    cudaGetSymbolAddress((void**)&p_col, g_col);
    cudaGetSymbolAddress((void**)&p_bs,  g_blksum);

    static cudaStream_t s_side = nullptr;
    static cudaEvent_t  ev_fork = nullptr, ev_join = nullptr;
    if (s_side == nullptr) {
        cudaStreamCreate(&s_side);
        cudaEventCreateWithFlags(&ev_fork, cudaEventDisableTiming);
        cudaEventCreateWithFlags(&ev_join, cudaEventDisableTiming);
    }

    const int GB_E4 = (NEDGES / 4 + 255) / 256;
    const int GB_W  = (NNODES * 32 + 255) / 256;
    const int GB_T  = (NNODES + 127) / 128;
    const int GB_N  = (NNODES + 255) / 256;
    const dim3 GB_G(GB_T, 2);
    const int n4x  = NNODES * NFEAT / 4;
    const int n4w1 = NHID * 2 * NFEAT / 4;
    const int n4w2 = NHID * 2 * NHID / 4;

    // ---- fork: CSR build on side stream (multi-block scan) ----
    cudaEventRecord(ev_fork, 0);
    cudaStreamWaitEvent(s_side, ev_fork, 0);
    cudaMemsetAsync(p_deg, 0, NNODES * sizeof(int), s_side);
    k_count<<<GB_E4, 256, 0, s_side>>>(rows, p_deg);
    k_scan1<<<SCAN_BLKS, 1024, 0, s_side>>>(p_deg, p_rp, p_bs);
    k_scan2<<<1, 128, 0, s_side>>>(p_bs);
    k_scan3<<<GB_N, 256, 0, s_side>>>(p_rp, p_cur, p_bs);
    k_fill<<<GB_E4, 256, 0, s_side>>>(rows, cols, p_cur, p_col);
    cudaEventRecord(ev_join, s_side);

    // ---- main: bf16 conversions + layer-1 GEMM ----
    k_cvt<<<(n4w1 + 255) / 256, 256>>>(W1, p_w1b, n4w1);
    k_cvt<<<(n4w2 + 255) / 256, 256>>>(W2, p_w2b, n4w2);
    k_cvt<<<(n4x + 255) / 256, 256>>>(x,  p_xb,  n4x);
    k_gemm_bf16<<<GB_G, 256>>>(p_xb, NFEAT, p_w1b, p_sh, p_zh);

    // ---- join: SpMM needs CSR + z + s ----
    cudaStreamWaitEvent(0, ev_join, 0);
    k_spmm<<<GB_W, 256>>>(p_zh, p_sh, p_rp, p_col, p_hb);

    // Layer 2
    k_gemm_bf16<<<GB_G, 256>>>(p_hb, NHID, p_w2b, p_sh, p_zh);
    k_spmm<<<GB_W, 256>>>(p_zh, p_sh, p_rp, p_col, p_hb);

    // MLP + log_softmax
    k_mlp_tc<<<GB_T, 128>>>(p_hb, mW, mb, out);
}